// round 10
// baseline (speedup 1.0000x reference)
#include <cuda_runtime.h>
#include <cuda_fp16.h>
#include <cstdint>

// ---------------------------------------------------------------------------
// Problem constants
// ---------------------------------------------------------------------------
#define BATCH   8
#define LQ      2048
#define LK      2048
#define IMG_DIM 1024
#define TXT_DIM 768
#define HID     1024

#define MQ (BATCH * LQ)
#define MK (BATCH * LK)

#define ZCHUNK  2
#define NCHUNK  (BATCH / ZCHUNK)

// ---------------------------------------------------------------------------
// Static scratch (~237 MB)
// ---------------------------------------------------------------------------
__device__ __half g_img[(size_t)MQ * IMG_DIM];
__device__ __half g_txt[(size_t)MK * TXT_DIM];
__device__ __half g_Wqt[(size_t)HID * IMG_DIM];
__device__ __half g_Wkt[(size_t)HID * TXT_DIM];
__device__ __half g_Wvt[(size_t)HID * TXT_DIM];
__device__ __half g_Qh[(size_t)MQ * HID];
__device__ __half g_Kh[(size_t)MK * HID];
__device__ __half g_Vh[(size_t)MK * HID];
__device__ __half g_Vt[(size_t)BATCH * HID * LK];
__device__ float  g_S[(size_t)ZCHUNK * LQ * LK];
__device__ __half g_P[(size_t)ZCHUNK * LQ * LK];

// ---------------------------------------------------------------------------
// Helpers
// ---------------------------------------------------------------------------
__device__ __forceinline__ void cp16s(uint32_t saddr, const void* src) {
    asm volatile("cp.async.cg.shared.global [%0], [%1], 16;" :: "r"(saddr), "l"(src));
}
#define CP_COMMIT() asm volatile("cp.async.commit_group;")

__device__ __forceinline__ void mma_f16(float* d, const uint32_t* a, const uint32_t* b) {
    asm volatile(
        "mma.sync.aligned.m16n8k16.row.col.f32.f16.f16.f32 "
        "{%0,%1,%2,%3}, {%4,%5,%6,%7}, {%8,%9}, {%0,%1,%2,%3};"
        : "+f"(d[0]), "+f"(d[1]), "+f"(d[2]), "+f"(d[3])
        : "r"(a[0]), "r"(a[1]), "r"(a[2]), "r"(a[3]),
          "r"(b[0]), "r"(b[1]));
}

__device__ __forceinline__ void ldsm_x4(uint32_t& r0, uint32_t& r1,
                                        uint32_t& r2, uint32_t& r3, uint32_t addr) {
    asm volatile("ldmatrix.sync.aligned.m8n8.x4.shared.b16 {%0,%1,%2,%3}, [%4];"
                 : "=r"(r0), "=r"(r1), "=r"(r2), "=r"(r3) : "r"(addr));
}

// ---------------------------------------------------------------------------
// FP16 NT GEMM: C[z] = alpha * A[z] @ B[z]^T (+ bias)
//   A row-major [M][K] half, B row-major [N][K] half (both K-contiguous).
// Tile BM=BN=128, BK=64; 256 threads (8 warps, 4M x 2N, warp 32x64);
// cp.async double-buffered (dynamic smem, 72 KB); ldmatrix fragment loads.
// Requires M,N % 128 == 0, K % 64 == 0, lda/ldb % 8 == 0.
// ---------------------------------------------------------------------------
#define GEMM_BM   128
#define GEMM_BK   64
#define GEMM_LDT  72                            // halves per smem row (144 B)
#define TILE_HBYTES (GEMM_BM * GEMM_LDT * 2)    // 18432 B per tile
#define STAGE_BYTES (2 * TILE_HBYTES)           // A + B = 36864 B
#define GEMM_SMEM   (2 * STAGE_BYTES)           // 73728 B

template <bool HAS_BIAS, bool OUT_HALF>
__global__ __launch_bounds__(256, 2)
void gemm_f16_nt(const __half* __restrict__ A, const __half* __restrict__ B,
                 const float* __restrict__ bias, void* __restrict__ Cv,
                 int K, int lda, int ldb, int ldc,
                 long sA, long sB, long sC, float alpha)
{
    constexpr int BM = GEMM_BM, BN = 128, BK = GEMM_BK, LDT = GEMM_LDT;
    extern __shared__ __half smem_dyn[];
    const uint32_t sbase = (uint32_t)__cvta_generic_to_shared(smem_dyn);

    const int bz = blockIdx.z;
    A += (long)bz * sA;
    B += (long)bz * sB;

    const int m0 = blockIdx.y * BM;
    const int n0 = blockIdx.x * BN;

    const int tid  = threadIdx.x;
    const int lane = tid & 31;
    const int warp = tid >> 5;
    const int gid  = lane >> 2;
    const int tid4 = lane & 3;
    const int wm   = warp & 3;
    const int wn   = warp >> 2;

    // gmem -> smem loaders: row = tid>>1, four 16B chunks starting at (tid&1)*4
    const int r_ld = tid >> 1;
    const int c0   = (tid & 1) * 4;
    const uint32_t row_off = r_ld * (LDT * 2);      // byte offset of row start

    // ldmatrix per-lane source rows/cols
    const int a_row = (lane & 7) + ((lane >> 3) & 1) * 8;
    const int a_kof = ((lane >> 4) & 1) * 8;
    const int b_row = (lane & 7) + ((lane >> 4) & 1) * 8;
    const int b_kof = ((lane >> 3) & 1) * 8;

    uint32_t a_off[2];
    #pragma unroll
    for (int mt = 0; mt < 2; mt++)
        a_off[mt] = ((wm * 32 + mt * 16 + a_row) * LDT + a_kof) * 2;
    uint32_t b_off[4];
    #pragma unroll
    for (int np = 0; np < 4; np++)
        b_off[np] = ((wn * 64 + np * 16 + b_row) * LDT + b_kof) * 2 + TILE_HBYTES;

    float acc[2][8][4] = {};
    const int nk = K / BK;

    // prologue: tile 0 into stage 0
    {
        const __half* a0 = A + (long)(m0 + r_ld) * lda + c0 * 8;
        const __half* b0 = B + (long)(n0 + r_ld) * ldb + c0 * 8;
        #pragma unroll
        for (int c = 0; c < 4; c++) {
            cp16s(sbase + row_off + (c0 + c) * 16,               a0 + c * 8);
            cp16s(sbase + TILE_HBYTES + row_off + (c0 + c) * 16, b0 + c * 8);
        }
    }
    CP_COMMIT();

    for (int kt = 0; kt < nk; kt++) {
        const int cur = kt & 1;
        if (kt + 1 < nk) {
            const int k0 = (kt + 1) * BK;
            const uint32_t st = sbase + (cur ^ 1) * STAGE_BYTES;
            const __half* a0 = A + (long)(m0 + r_ld) * lda + k0 + c0 * 8;
            const __half* b0 = B + (long)(n0 + r_ld) * ldb + k0 + c0 * 8;
            #pragma unroll
            for (int c = 0; c < 4; c++) {
                cp16s(st + row_off + (c0 + c) * 16,               a0 + c * 8);
                cp16s(st + TILE_HBYTES + row_off + (c0 + c) * 16, b0 + c * 8);
            }
        }
        CP_COMMIT();
        asm volatile("cp.async.wait_group 1;");
        __syncthreads();

        const uint32_t st = sbase + cur * STAGE_BYTES;

        #pragma unroll
        for (int ks = 0; ks < BK / 16; ks++) {
            const uint32_t kb = ks * 16 * 2;     // k16-step byte offset
            uint32_t af[2][4], bf[8][2];
            #pragma unroll
            for (int mt = 0; mt < 2; mt++)
                ldsm_x4(af[mt][0], af[mt][1], af[mt][2], af[mt][3],
                        st + a_off[mt] + kb);
            #pragma unroll
            for (int np = 0; np < 4; np++)
                ldsm_x4(bf[2*np][0], bf[2*np][1], bf[2*np+1][0], bf[2*np+1][1],
                        st + b_off[np] + kb);
            #pragma unroll
            for (int mt = 0; mt < 2; mt++)
                #pragma unroll
                for (int nt = 0; nt < 8; nt++)
                    mma_f16(acc[mt][nt], af[mt], bf[nt]);
        }
        __syncthreads();
    }

    // ---- epilogue ----
    #pragma unroll
    for (int mt = 0; mt < 2; mt++) {
        #pragma unroll
        for (int nt = 0; nt < 8; nt++) {
            const int col = n0 + wn * 64 + nt * 8 + 2 * tid4;
            float b0 = 0.f, b1 = 0.f;
            if (HAS_BIAS) { b0 = bias[col]; b1 = bias[col + 1]; }
            const int r0 = m0 + wm * 32 + mt * 16 + gid;
            float v00 = alpha * acc[mt][nt][0] + b0;
            float v01 = alpha * acc[mt][nt][1] + b1;
            float v10 = alpha * acc[mt][nt][2] + b0;
            float v11 = alpha * acc[mt][nt][3] + b1;
            if (OUT_HALF) {
                __half* C = (__half*)Cv + (long)bz * sC;
                __half2 h0 = __floats2half2_rn(v00, v01);
                __half2 h1 = __floats2half2_rn(v10, v11);
                *reinterpret_cast<__half2*>(&C[(long)r0 * ldc + col])       = h0;
                *reinterpret_cast<__half2*>(&C[(long)(r0 + 8) * ldc + col]) = h1;
            } else {
                float* C = (float*)Cv + (long)bz * sC;
                *reinterpret_cast<float2*>(&C[(long)r0 * ldc + col])       = make_float2(v00, v01);
                *reinterpret_cast<float2*>(&C[(long)(r0 + 8) * ldc + col]) = make_float2(v10, v11);
            }
        }
    }
}

// ---------------------------------------------------------------------------
// float -> half elementwise
// ---------------------------------------------------------------------------
__global__ __launch_bounds__(256)
void f2h_kernel(const float* __restrict__ s, __half* __restrict__ d, long n4)
{
    long i = blockIdx.x * (long)blockDim.x + threadIdx.x;
    if (i < n4) {
        float4 v = reinterpret_cast<const float4*>(s)[i];
        __half2 h0 = __floats2half2_rn(v.x, v.y);
        __half2 h1 = __floats2half2_rn(v.z, v.w);
        uint2 u;
        u.x = *reinterpret_cast<uint32_t*>(&h0);
        u.y = *reinterpret_cast<uint32_t*>(&h1);
        reinterpret_cast<uint2*>(d)[i] = u;
    }
}

// ---------------------------------------------------------------------------
// Weight transpose + convert: src float [R][C] -> dst half [C][R]
// ---------------------------------------------------------------------------
__global__ __launch_bounds__(256)
void transpose_f2h(const float* __restrict__ src, __half* __restrict__ dst,
                   int R, int C)
{
    __shared__ float t[32][33];
    const int tx = threadIdx.x, ty = threadIdx.y;
    const int xb = blockIdx.x * 32, yb = blockIdx.y * 32;
    #pragma unroll
    for (int j = 0; j < 4; j++)
        t[ty + 8 * j][tx] = src[(long)(yb + ty + 8 * j) * C + xb + tx];
    __syncthreads();
    #pragma unroll
    for (int j = 0; j < 4; j++)
        dst[(long)(xb + ty + 8 * j) * R + yb + tx] = __float2half(t[tx][ty + 8 * j]);
}

// ---------------------------------------------------------------------------
// Half transpose (batched): src [z][R][C] -> dst [z][C][R]
// ---------------------------------------------------------------------------
__global__ __launch_bounds__(256)
void transpose_h64(const __half* __restrict__ src, __half* __restrict__ dst,
                   int R, int C)
{
    __shared__ __half t[64][65];
    const long zoff = (long)blockIdx.z * R * C;
    src += zoff; dst += zoff;
    const int tx = threadIdx.x, ty = threadIdx.y;
    const int xb = blockIdx.x * 64, yb = blockIdx.y * 64;
    #pragma unroll
    for (int j = 0; j < 8; j++) {
        int y = yb + ty + 8 * j;
        __half2 v = *reinterpret_cast<const __half2*>(&src[(long)y * C + xb + 2 * tx]);
        t[2 * tx][ty + 8 * j]     = __low2half(v);
        t[2 * tx + 1][ty + 8 * j] = __high2half(v);
    }
    __syncthreads();
    #pragma unroll
    for (int j = 0; j < 8; j++) {
        int c = ty + 8 * j;
        __half2 w = __halves2half2(t[c][2 * tx], t[c][2 * tx + 1]);
        *reinterpret_cast<__half2*>(&dst[(long)(xb + c) * R + yb + 2 * tx]) = w;
    }
}

// ---------------------------------------------------------------------------
// Row softmax over 2048-wide float rows -> half output
// ---------------------------------------------------------------------------
__global__ __launch_bounds__(256)
void softmax2048_h(const float* __restrict__ S, __half* __restrict__ P)
{
    const long row = blockIdx.x;
    const float* p = S + row * (long)LK;
    __half* q = P + row * (long)LK;
    const int tid = threadIdx.x;

    float4 a = reinterpret_cast<const float4*>(p)[tid];
    float4 b = reinterpret_cast<const float4*>(p)[tid + 256];

    float mx = fmaxf(fmaxf(fmaxf(a.x, a.y), fmaxf(a.z, a.w)),
                     fmaxf(fmaxf(b.x, b.y), fmaxf(b.z, b.w)));
    #pragma unroll
    for (int o = 16; o; o >>= 1) mx = fmaxf(mx, __shfl_xor_sync(0xffffffffu, mx, o));
    __shared__ float smax[8];
    if ((tid & 31) == 0) smax[tid >> 5] = mx;
    __syncthreads();
    mx = smax[0];
    #pragma unroll
    for (int i = 1; i < 8; i++) mx = fmaxf(mx, smax[i]);

    a.x = __expf(a.x - mx); a.y = __expf(a.y - mx);
    a.z = __expf(a.z - mx); a.w = __expf(a.w - mx);
    b.x = __expf(b.x - mx); b.y = __expf(b.y - mx);
    b.z = __expf(b.z - mx); b.w = __expf(b.w - mx);
    float sum = (a.x + a.y + a.z + a.w) + (b.x + b.y + b.z + b.w);
    #pragma unroll
    for (int o = 16; o; o >>= 1) sum += __shfl_xor_sync(0xffffffffu, sum, o);
    __shared__ float ssum[8];
    if ((tid & 31) == 0) ssum[tid >> 5] = sum;
    __syncthreads();
    sum = 0.f;
    #pragma unroll
    for (int i = 0; i < 8; i++) sum += ssum[i];

    const float inv = 1.0f / sum;
    __half2 h0 = __floats2half2_rn(a.x * inv, a.y * inv);
    __half2 h1 = __floats2half2_rn(a.z * inv, a.w * inv);
    __half2 h2 = __floats2half2_rn(b.x * inv, b.y * inv);
    __half2 h3 = __floats2half2_rn(b.z * inv, b.w * inv);
    uint2 u0, u1;
    u0.x = *reinterpret_cast<uint32_t*>(&h0);
    u0.y = *reinterpret_cast<uint32_t*>(&h1);
    u1.x = *reinterpret_cast<uint32_t*>(&h2);
    u1.y = *reinterpret_cast<uint32_t*>(&h3);
    reinterpret_cast<uint2*>(q)[tid]       = u0;
    reinterpret_cast<uint2*>(q)[tid + 256] = u1;
}

// ---------------------------------------------------------------------------
// Launch
// ---------------------------------------------------------------------------
extern "C" void kernel_launch(void* const* d_in, const int* in_sizes, int n_in,
                              void* d_out, int out_size)
{
    const float* img = (const float*)d_in[0];
    const float* txt = (const float*)d_in[1];
    const float* Wq  = (const float*)d_in[2];
    const float* bq  = (const float*)d_in[3];
    const float* Wk  = (const float*)d_in[4];
    const float* bk  = (const float*)d_in[5];
    const float* Wv  = (const float*)d_in[6];
    const float* bv  = (const float*)d_in[7];
    float* out = (float*)d_out;

    __half *imgh, *txth, *Wqt, *Wkt, *Wvt, *Qh, *Kh, *Vh, *Vt, *Pb;
    float *Sb;
    cudaGetSymbolAddress((void**)&imgh, g_img);
    cudaGetSymbolAddress((void**)&txth, g_txt);
    cudaGetSymbolAddress((void**)&Wqt, g_Wqt);
    cudaGetSymbolAddress((void**)&Wkt, g_Wkt);
    cudaGetSymbolAddress((void**)&Wvt, g_Wvt);
    cudaGetSymbolAddress((void**)&Qh, g_Qh);
    cudaGetSymbolAddress((void**)&Kh, g_Kh);
    cudaGetSymbolAddress((void**)&Vh, g_Vh);
    cudaGetSymbolAddress((void**)&Vt, g_Vt);
    cudaGetSymbolAddress((void**)&Sb, g_S);
    cudaGetSymbolAddress((void**)&Pb, g_P);

    // Allow 72 KB dynamic smem on the GEMM (attribute set; not a stream op,
    // safe under graph capture; idempotent across calls).
    cudaFuncSetAttribute(gemm_f16_nt<true, true>,
                         cudaFuncAttributeMaxDynamicSharedMemorySize, GEMM_SMEM);
    cudaFuncSetAttribute(gemm_f16_nt<false, false>,
                         cudaFuncAttributeMaxDynamicSharedMemorySize, GEMM_SMEM);

    const dim3 blk(256);

    // ---- convert activations to half ----
    {
        long n4 = (long)MQ * IMG_DIM / 4;
        f2h_kernel<<<(unsigned)((n4 + 255) / 256), blk>>>(img, imgh, n4);
        n4 = (long)MK * TXT_DIM / 4;
        f2h_kernel<<<(unsigned)((n4 + 255) / 256), blk>>>(txt, txth, n4);
    }

    // ---- transpose + convert weights: [K][HID] float -> [HID][K] half ----
    transpose_f2h<<<dim3(HID / 32, IMG_DIM / 32), dim3(32, 8)>>>(Wq, Wqt, IMG_DIM, HID);
    transpose_f2h<<<dim3(HID / 32, TXT_DIM / 32), dim3(32, 8)>>>(Wk, Wkt, TXT_DIM, HID);
    transpose_f2h<<<dim3(HID / 32, TXT_DIM / 32), dim3(32, 8)>>>(Wv, Wvt, TXT_DIM, HID);

    // ---- projections (NT, half out) ----
    gemm_f16_nt<true, true><<<dim3(HID / 128, MQ / 128, 1), blk, GEMM_SMEM>>>(
        imgh, Wqt, bq, Qh, IMG_DIM, IMG_DIM, IMG_DIM, HID, 0, 0, 0, 1.0f);
    gemm_f16_nt<true, true><<<dim3(HID / 128, MK / 128, 1), blk, GEMM_SMEM>>>(
        txth, Wkt, bk, Kh, TXT_DIM, TXT_DIM, TXT_DIM, HID, 0, 0, 0, 1.0f);
    gemm_f16_nt<true, true><<<dim3(HID / 128, MK / 128, 1), blk, GEMM_SMEM>>>(
        txth, Wvt, bv, Vh, TXT_DIM, TXT_DIM, TXT_DIM, HID, 0, 0, 0, 1.0f);

    // ---- V transpose: [z][LK][HID] -> [z][HID][LK] ----
    transpose_h64<<<dim3(HID / 64, LK / 64, BATCH), dim3(32, 8)>>>(Vh, Vt, LK, HID);

    // ---- attention in chunks of ZCHUNK batches ----
    for (int c = 0; c < NCHUNK; c++) {
        const long zoff = (long)c * ZCHUNK;
        // S = (1/sqrt(HID)) * Q @ K^T
        gemm_f16_nt<false, false><<<dim3(LK / 128, LQ / 128, ZCHUNK), blk, GEMM_SMEM>>>(
            Qh + zoff * LQ * HID, Kh + zoff * LK * HID, nullptr, Sb,
            HID, HID, HID, LK,
            (long)LQ * HID, (long)LK * HID, (long)LQ * LK, 0.03125f);
        // P = softmax(S) (half)
        softmax2048_h<<<ZCHUNK * LQ, blk>>>(Sb, Pb);
        // O = P @ Vt^T
        gemm_f16_nt<false, false><<<dim3(HID / 128, LQ / 128, ZCHUNK), blk, GEMM_SMEM>>>(
            Pb, Vt + zoff * HID * LK, nullptr, out + zoff * LQ * HID,
            LK, LK, LK, HID,
            (long)LQ * LK, (long)HID * LK, (long)LQ * HID, 1.0f);
    }
}

// round 12
// speedup vs baseline: 1.2189x; 1.2189x over previous
// R11 resubmit of the 4-stage-pipeline variant (R11 container failure was the
// recurring broker flake; R4/R5 byte-identical pair proved content-independence).
#include <cuda_runtime.h>
#include <cuda_fp16.h>
#include <cstdint>

// ---------------------------------------------------------------------------
// Problem constants
// ---------------------------------------------------------------------------
#define BATCH   8
#define LQ      2048
#define LK      2048
#define IMG_DIM 1024
#define TXT_DIM 768
#define HID     1024

#define MQ (BATCH * LQ)
#define MK (BATCH * LK)

#define ZCHUNK  2
#define NCHUNK  (BATCH / ZCHUNK)

// ---------------------------------------------------------------------------
// Static scratch (~237 MB)
// ---------------------------------------------------------------------------
__device__ __half g_img[(size_t)MQ * IMG_DIM];
__device__ __half g_txt[(size_t)MK * TXT_DIM];
__device__ __half g_Wqt[(size_t)HID * IMG_DIM];
__device__ __half g_Wkt[(size_t)HID * TXT_DIM];
__device__ __half g_Wvt[(size_t)HID * TXT_DIM];
__device__ __half g_Qh[(size_t)MQ * HID];
__device__ __half g_Kh[(size_t)MK * HID];
__device__ __half g_Vh[(size_t)MK * HID];
__device__ __half g_Vt[(size_t)BATCH * HID * LK];
__device__ float  g_S[(size_t)ZCHUNK * LQ * LK];
__device__ __half g_P[(size_t)ZCHUNK * LQ * LK];

// ---------------------------------------------------------------------------
// Helpers
// ---------------------------------------------------------------------------
__device__ __forceinline__ void cp16s(uint32_t saddr, const void* src) {
    asm volatile("cp.async.cg.shared.global [%0], [%1], 16;" :: "r"(saddr), "l"(src));
}
#define CP_COMMIT() asm volatile("cp.async.commit_group;")

__device__ __forceinline__ void mma_f16(float* d, const uint32_t* a, const uint32_t* b) {
    asm volatile(
        "mma.sync.aligned.m16n8k16.row.col.f32.f16.f16.f32 "
        "{%0,%1,%2,%3}, {%4,%5,%6,%7}, {%8,%9}, {%0,%1,%2,%3};"
        : "+f"(d[0]), "+f"(d[1]), "+f"(d[2]), "+f"(d[3])
        : "r"(a[0]), "r"(a[1]), "r"(a[2]), "r"(a[3]),
          "r"(b[0]), "r"(b[1]));
}

__device__ __forceinline__ void ldsm_x4(uint32_t& r0, uint32_t& r1,
                                        uint32_t& r2, uint32_t& r3, uint32_t addr) {
    asm volatile("ldmatrix.sync.aligned.m8n8.x4.shared.b16 {%0,%1,%2,%3}, [%4];"
                 : "=r"(r0), "=r"(r1), "=r"(r2), "=r"(r3) : "r"(addr));
}

// ---------------------------------------------------------------------------
// FP16 NT GEMM: C[z] = alpha * A[z] @ B[z]^T (+ bias)
//   A row-major [M][K] half, B row-major [N][K] half (both K-contiguous).
// Tile BM=BN=128, BK=32; 256 threads (8 warps, 4M x 2N, warp 32x64);
// 4-stage cp.async pipeline (prefetch distance 3, ONE barrier/iter);
// ldmatrix fragment loads. Requires M,N%128==0, K%32==0, lda/ldb%8==0.
// ---------------------------------------------------------------------------
#define GEMM_LDT    40                           // halves per smem row (80 B)
#define TILE_HB     (128 * GEMM_LDT * 2)         // 10240 B per tile
#define STAGE_BYTES (2 * TILE_HB)                // A + B = 20480 B
#define GEMM_SMEM   (4 * STAGE_BYTES)            // 81920 B

template <bool HAS_BIAS, bool OUT_HALF>
__global__ __launch_bounds__(256, 2)
void gemm_f16_nt(const __half* __restrict__ A, const __half* __restrict__ B,
                 const float* __restrict__ bias, void* __restrict__ Cv,
                 int K, int lda, int ldb, int ldc,
                 long sA, long sB, long sC, float alpha)
{
    constexpr int BM = 128, BN = 128, BK = 32, LDT = GEMM_LDT;
    extern __shared__ __half smem_dyn[];
    const uint32_t sbase = (uint32_t)__cvta_generic_to_shared(smem_dyn);

    const int bz = blockIdx.z;
    A += (long)bz * sA;
    B += (long)bz * sB;

    const int m0 = blockIdx.y * BM;
    const int n0 = blockIdx.x * BN;

    const int tid  = threadIdx.x;
    const int lane = tid & 31;
    const int warp = tid >> 5;
    const int gid  = lane >> 2;
    const int tid4 = lane & 3;
    const int wm   = warp & 3;
    const int wn   = warp >> 2;

    // gmem -> smem loaders: row = tid>>1, two 16B chunks at (tid&1)*2
    const int r_ld = tid >> 1;
    const int c0   = (tid & 1) * 2;
    const uint32_t row_off = r_ld * (LDT * 2);

    // ldmatrix per-lane source rows/cols
    const int a_row = (lane & 7) + ((lane >> 3) & 1) * 8;
    const int a_kof = ((lane >> 4) & 1) * 8;
    const int b_row = (lane & 7) + ((lane >> 4) & 1) * 8;
    const int b_kof = ((lane >> 3) & 1) * 8;

    uint32_t a_off[2];
    #pragma unroll
    for (int mt = 0; mt < 2; mt++)
        a_off[mt] = ((wm * 32 + mt * 16 + a_row) * LDT + a_kof) * 2;
    uint32_t b_off[4];
    #pragma unroll
    for (int np = 0; np < 4; np++)
        b_off[np] = ((wn * 64 + np * 16 + b_row) * LDT + b_kof) * 2 + TILE_HB;

    float acc[2][8][4] = {};
    const int nk = K / BK;        // >= 24 for all shapes here

    // ---- prologue: prefetch tiles 0,1,2 into stages 0,1,2 (3 groups) ----
    #pragma unroll
    for (int p = 0; p < 3; p++) {
        const int k0 = p * BK;
        const uint32_t st = sbase + p * STAGE_BYTES;
        const __half* a0 = A + (long)(m0 + r_ld) * lda + k0 + c0 * 8;
        const __half* b0 = B + (long)(n0 + r_ld) * ldb + k0 + c0 * 8;
        cp16s(st + row_off + c0 * 16,                a0);
        cp16s(st + row_off + c0 * 16 + 16,           a0 + 8);
        cp16s(st + TILE_HB + row_off + c0 * 16,      b0);
        cp16s(st + TILE_HB + row_off + c0 * 16 + 16, b0 + 8);
        CP_COMMIT();
    }

    for (int kt = 0; kt < nk; kt++) {
        // tile kt's group is complete once <=2 groups remain outstanding
        asm volatile("cp.async.wait_group 2;");
        __syncthreads();

        const uint32_t st = sbase + (kt & 3) * STAGE_BYTES;

        #pragma unroll
        for (int ks = 0; ks < 2; ks++) {
            const uint32_t kb = ks * 16 * 2;
            uint32_t af[2][4], bf[8][2];
            #pragma unroll
            for (int mt = 0; mt < 2; mt++)
                ldsm_x4(af[mt][0], af[mt][1], af[mt][2], af[mt][3],
                        st + a_off[mt] + kb);
            #pragma unroll
            for (int np = 0; np < 4; np++)
                ldsm_x4(bf[2*np][0], bf[2*np][1], bf[2*np+1][0], bf[2*np+1][1],
                        st + b_off[np] + kb);
            #pragma unroll
            for (int mt = 0; mt < 2; mt++)
                #pragma unroll
                for (int nt = 0; nt < 8; nt++)
                    mma_f16(acc[mt][nt], af[mt], bf[nt]);
        }

        // prefetch tile kt+3 into stage (kt+3)&3 == (kt-1)&3 (read finished
        // by all warps before this iteration's barrier)
        if (kt + 3 < nk) {
            const int k0 = (kt + 3) * BK;
            const uint32_t pst = sbase + ((kt + 3) & 3) * STAGE_BYTES;
            const __half* a0 = A + (long)(m0 + r_ld) * lda + k0 + c0 * 8;
            const __half* b0 = B + (long)(n0 + r_ld) * ldb + k0 + c0 * 8;
            cp16s(pst + row_off + c0 * 16,                a0);
            cp16s(pst + row_off + c0 * 16 + 16,           a0 + 8);
            cp16s(pst + TILE_HB + row_off + c0 * 16,      b0);
            cp16s(pst + TILE_HB + row_off + c0 * 16 + 16, b0 + 8);
        }
        CP_COMMIT();
    }

    // ---- epilogue ----
    #pragma unroll
    for (int mt = 0; mt < 2; mt++) {
        #pragma unroll
        for (int nt = 0; nt < 8; nt++) {
            const int col = n0 + wn * 64 + nt * 8 + 2 * tid4;
            float b0 = 0.f, b1 = 0.f;
            if (HAS_BIAS) { b0 = bias[col]; b1 = bias[col + 1]; }
            const int r0 = m0 + wm * 32 + mt * 16 + gid;
            float v00 = alpha * acc[mt][nt][0] + b0;
            float v01 = alpha * acc[mt][nt][1] + b1;
            float v10 = alpha * acc[mt][nt][2] + b0;
            float v11 = alpha * acc[mt][nt][3] + b1;
            if (OUT_HALF) {
                __half* C = (__half*)Cv + (long)bz * sC;
                __half2 h0 = __floats2half2_rn(v00, v01);
                __half2 h1 = __floats2half2_rn(v10, v11);
                *reinterpret_cast<__half2*>(&C[(long)r0 * ldc + col])       = h0;
                *reinterpret_cast<__half2*>(&C[(long)(r0 + 8) * ldc + col]) = h1;
            } else {
                float* C = (float*)Cv + (long)bz * sC;
                *reinterpret_cast<float2*>(&C[(long)r0 * ldc + col])       = make_float2(v00, v01);
                *reinterpret_cast<float2*>(&C[(long)(r0 + 8) * ldc + col]) = make_float2(v10, v11);
            }
        }
    }
}

// ---------------------------------------------------------------------------
// float -> half elementwise
// ---------------------------------------------------------------------------
__global__ __launch_bounds__(256)
void f2h_kernel(const float* __restrict__ s, __half* __restrict__ d, long n4)
{
    long i = blockIdx.x * (long)blockDim.x + threadIdx.x;
    if (i < n4) {
        float4 v = reinterpret_cast<const float4*>(s)[i];
        __half2 h0 = __floats2half2_rn(v.x, v.y);
        __half2 h1 = __floats2half2_rn(v.z, v.w);
        uint2 u;
        u.x = *reinterpret_cast<uint32_t*>(&h0);
        u.y = *reinterpret_cast<uint32_t*>(&h1);
        reinterpret_cast<uint2*>(d)[i] = u;
    }
}

// ---------------------------------------------------------------------------
// Weight transpose + convert: src float [R][C] -> dst half [C][R]
// ---------------------------------------------------------------------------
__global__ __launch_bounds__(256)
void transpose_f2h(const float* __restrict__ src, __half* __restrict__ dst,
                   int R, int C)
{
    __shared__ float t[32][33];
    const int tx = threadIdx.x, ty = threadIdx.y;
    const int xb = blockIdx.x * 32, yb = blockIdx.y * 32;
    #pragma unroll
    for (int j = 0; j < 4; j++)
        t[ty + 8 * j][tx] = src[(long)(yb + ty + 8 * j) * C + xb + tx];
    __syncthreads();
    #pragma unroll
    for (int j = 0; j < 4; j++)
        dst[(long)(xb + ty + 8 * j) * R + yb + tx] = __float2half(t[tx][ty + 8 * j]);
}

// ---------------------------------------------------------------------------
// Half transpose (batched): src [z][R][C] -> dst [z][C][R]
// ---------------------------------------------------------------------------
__global__ __launch_bounds__(256)
void transpose_h64(const __half* __restrict__ src, __half* __restrict__ dst,
                   int R, int C)
{
    __shared__ __half t[64][65];
    const long zoff = (long)blockIdx.z * R * C;
    src += zoff; dst += zoff;
    const int tx = threadIdx.x, ty = threadIdx.y;
    const int xb = blockIdx.x * 64, yb = blockIdx.y * 64;
    #pragma unroll
    for (int j = 0; j < 8; j++) {
        int y = yb + ty + 8 * j;
        __half2 v = *reinterpret_cast<const __half2*>(&src[(long)y * C + xb + 2 * tx]);
        t[2 * tx][ty + 8 * j]     = __low2half(v);
        t[2 * tx + 1][ty + 8 * j] = __high2half(v);
    }
    __syncthreads();
    #pragma unroll
    for (int j = 0; j < 8; j++) {
        int c = ty + 8 * j;
        __half2 w = __halves2half2(t[c][2 * tx], t[c][2 * tx + 1]);
        *reinterpret_cast<__half2*>(&dst[(long)(xb + c) * R + yb + 2 * tx]) = w;
    }
}

// ---------------------------------------------------------------------------
// Row softmax over 2048-wide float rows -> half output
// ---------------------------------------------------------------------------
__global__ __launch_bounds__(256)
void softmax2048_h(const float* __restrict__ S, __half* __restrict__ P)
{
    const long row = blockIdx.x;
    const float* p = S + row * (long)LK;
    __half* q = P + row * (long)LK;
    const int tid = threadIdx.x;

    float4 a = reinterpret_cast<const float4*>(p)[tid];
    float4 b = reinterpret_cast<const float4*>(p)[tid + 256];

    float mx = fmaxf(fmaxf(fmaxf(a.x, a.y), fmaxf(a.z, a.w)),
                     fmaxf(fmaxf(b.x, b.y), fmaxf(b.z, b.w)));
    #pragma unroll
    for (int o = 16; o; o >>= 1) mx = fmaxf(mx, __shfl_xor_sync(0xffffffffu, mx, o));
    __shared__ float smax[8];
    if ((tid & 31) == 0) smax[tid >> 5] = mx;
    __syncthreads();
    mx = smax[0];
    #pragma unroll
    for (int i = 1; i < 8; i++) mx = fmaxf(mx, smax[i]);

    a.x = __expf(a.x - mx); a.y = __expf(a.y - mx);
    a.z = __expf(a.z - mx); a.w = __expf(a.w - mx);
    b.x = __expf(b.x - mx); b.y = __expf(b.y - mx);
    b.z = __expf(b.z - mx); b.w = __expf(b.w - mx);
    float sum = (a.x + a.y + a.z + a.w) + (b.x + b.y + b.z + b.w);
    #pragma unroll
    for (int o = 16; o; o >>= 1) sum += __shfl_xor_sync(0xffffffffu, sum, o);
    __shared__ float ssum[8];
    if ((tid & 31) == 0) ssum[tid >> 5] = sum;
    __syncthreads();
    sum = 0.f;
    #pragma unroll
    for (int i = 0; i < 8; i++) sum += ssum[i];

    const float inv = 1.0f / sum;
    __half2 h0 = __floats2half2_rn(a.x * inv, a.y * inv);
    __half2 h1 = __floats2half2_rn(a.z * inv, a.w * inv);
    __half2 h2 = __floats2half2_rn(b.x * inv, b.y * inv);
    __half2 h3 = __floats2half2_rn(b.z * inv, b.w * inv);
    uint2 u0, u1;
    u0.x = *reinterpret_cast<uint32_t*>(&h0);
    u0.y = *reinterpret_cast<uint32_t*>(&h1);
    u1.x = *reinterpret_cast<uint32_t*>(&h2);
    u1.y = *reinterpret_cast<uint32_t*>(&h3);
    reinterpret_cast<uint2*>(q)[tid]       = u0;
    reinterpret_cast<uint2*>(q)[tid + 256] = u1;
}

// ---------------------------------------------------------------------------
// Launch
// ---------------------------------------------------------------------------
extern "C" void kernel_launch(void* const* d_in, const int* in_sizes, int n_in,
                              void* d_out, int out_size)
{
    const float* img = (const float*)d_in[0];
    const float* txt = (const float*)d_in[1];
    const float* Wq  = (const float*)d_in[2];
    const float* bq  = (const float*)d_in[3];
    const float* Wk  = (const float*)d_in[4];
    const float* bk  = (const float*)d_in[5];
    const float* Wv  = (const float*)d_in[6];
    const float* bv  = (const float*)d_in[7];
    float* out = (float*)d_out;

    __half *imgh, *txth, *Wqt, *Wkt, *Wvt, *Qh, *Kh, *Vh, *Vt, *Pb;
    float *Sb;
    cudaGetSymbolAddress((void**)&imgh, g_img);
    cudaGetSymbolAddress((void**)&txth, g_txt);
    cudaGetSymbolAddress((void**)&Wqt, g_Wqt);
    cudaGetSymbolAddress((void**)&Wkt, g_Wkt);
    cudaGetSymbolAddress((void**)&Wvt, g_Wvt);
    cudaGetSymbolAddress((void**)&Qh, g_Qh);
    cudaGetSymbolAddress((void**)&Kh, g_Kh);
    cudaGetSymbolAddress((void**)&Vh, g_Vh);
    cudaGetSymbolAddress((void**)&Vt, g_Vt);
    cudaGetSymbolAddress((void**)&Sb, g_S);
    cudaGetSymbolAddress((void**)&Pb, g_P);

    // 80 KB dynamic smem for the GEMM (attribute set; capture-safe; idempotent)
    cudaFuncSetAttribute(gemm_f16_nt<true, true>,
                         cudaFuncAttributeMaxDynamicSharedMemorySize, GEMM_SMEM);
    cudaFuncSetAttribute(gemm_f16_nt<false, false>,
                         cudaFuncAttributeMaxDynamicSharedMemorySize, GEMM_SMEM);

    const dim3 blk(256);

    // ---- convert activations to half ----
    {
        long n4 = (long)MQ * IMG_DIM / 4;
        f2h_kernel<<<(unsigned)((n4 + 255) / 256), blk>>>(img, imgh, n4);
        n4 = (long)MK * TXT_DIM / 4;
        f2h_kernel<<<(unsigned)((n4 + 255) / 256), blk>>>(txt, txth, n4);
    }

    // ---- transpose + convert weights: [K][HID] float -> [HID][K] half ----
    transpose_f2h<<<dim3(HID / 32, IMG_DIM / 32), dim3(32, 8)>>>(Wq, Wqt, IMG_DIM, HID);
    transpose_f2h<<<dim3(HID / 32, TXT_DIM / 32), dim3(32, 8)>>>(Wk, Wkt, TXT_DIM, HID);
    transpose_f2h<<<dim3(HID / 32, TXT_DIM / 32), dim3(32, 8)>>>(Wv, Wvt, TXT_DIM, HID);

    // ---- projections (NT, half out) ----
    gemm_f16_nt<true, true><<<dim3(HID / 128, MQ / 128, 1), blk, GEMM_SMEM>>>(
        imgh, Wqt, bq, Qh, IMG_DIM, IMG_DIM, IMG_DIM, HID, 0, 0, 0, 1.0f);
    gemm_f16_nt<true, true><<<dim3(HID / 128, MK / 128, 1), blk, GEMM_SMEM>>>(
        txth, Wkt, bk, Kh, TXT_DIM, TXT_DIM, TXT_DIM, HID, 0, 0, 0, 1.0f);
    gemm_f16_nt<true, true><<<dim3(HID / 128, MK / 128, 1), blk, GEMM_SMEM>>>(
        txth, Wvt, bv, Vh, TXT_DIM, TXT_DIM, TXT_DIM, HID, 0, 0, 0, 1.0f);

    // ---- V transpose: [z][LK][HID] -> [z][HID][LK] ----
    transpose_h64<<<dim3(HID / 64, LK / 64, BATCH), dim3(32, 8)>>>(Vh, Vt, LK, HID);

    // ---- attention in chunks of ZCHUNK batches ----
    for (int c = 0; c < NCHUNK; c++) {
        const long zoff = (long)c * ZCHUNK;
        // S = (1/sqrt(HID)) * Q @ K^T
        gemm_f16_nt<false, false><<<dim3(LK / 128, LQ / 128, ZCHUNK), blk, GEMM_SMEM>>>(
            Qh + zoff * LQ * HID, Kh + zoff * LK * HID, nullptr, Sb,
            HID, HID, HID, LK,
            (long)LQ * HID, (long)LK * HID, (long)LQ * LK, 0.03125f);
        // P = softmax(S) (half)
        softmax2048_h<<<ZCHUNK * LQ, blk>>>(Sb, Pb);
        // O = P @ Vt^T
        gemm_f16_nt<false, false><<<dim3(HID / 128, LQ / 128, ZCHUNK), blk, GEMM_SMEM>>>(
            Pb, Vt + zoff * HID * LK, nullptr, out + zoff * LQ * HID,
            LK, LK, LK, HID,
            (long)LQ * LK, (long)HID * LK, (long)LQ * HID, 1.0f);
    }
}